// round 6
// baseline (speedup 1.0000x reference)
#include <cuda_runtime.h>
#include <math.h>
#include <float.h>

#define BB   16
#define NN   4096
#define KK   4096
#define NCHUNK 4
#define CHUNK  1024      // NN / NCHUNK
#define IN1  16384
#define H1   1024
#define H2   512
#define OUTD 256

typedef unsigned long long ull;

#define FMA2(out, a, b, c) asm("fma.rn.f32x2 %0, %1, %2, %3;" : "=l"(out) : "l"(a), "l"(b), "l"(c))
#define MUL2(out, a, b)    asm("mul.rn.f32x2 %0, %1, %2;"     : "=l"(out) : "l"(a), "l"(b))
#define ADD2(out, a, b)    asm("add.rn.f32x2 %0, %1, %2;"     : "=l"(out) : "l"(a), "l"(b))

__device__ __forceinline__ ull pk2(float lo, float hi) {
    ull r; asm("mov.b64 %0, {%1, %2};" : "=l"(r) : "f"(lo), "f"(hi)); return r;
}
__device__ __forceinline__ void upk2(float& lo, float& hi, ull v) {
    asm("mov.b64 {%0, %1}, %2;" : "=f"(lo), "=f"(hi) : "l"(v));
}

// ---- scratch ----
__device__ float g_best[BB * KK * NCHUNK];
__device__ int   g_bidx[BB * KK * NCHUNK];
__device__ float g_part1[128 * BB * H1];      // 8 MB
__device__ float g_tmp  [16 * BB * H1];       // 1 MB (stage-1 partials)
__device__ float g_h1[BB * H1];
__device__ float g_part2[64 * BB * H2];       // 2 MB
__device__ float g_h2[BB * H2];
__device__ float g_part3[16 * BB * OUTD];

// ============================================================
// Kernel 1: partial argmin over an N-chunk, bit-exact reference
// arithmetic, 2 pts per f32x2 op, GROUP-OF-8 deferred min.
//   spA[i] = {-2x(2i), -2x(2i+1), -2y(2i), -2y(2i+1)}
//   spB[i] = {-2z(2i), -2z(2i+1),  pn(2i),  pn(2i+1)}
//   d = rn(fma(bz,-2z,fma(by,-2y,rn(bx*-2x))) + rn(bn+pn))
//     == reference fma(-2,cr,bn+pn) bit-exactly.
// grid: (KK/256, NCHUNK, BB), block 256
// ============================================================
__global__ void k_argmin(const float* __restrict__ pc,
                         const float* __restrict__ basis) {
    __shared__ __align__(16) ulonglong2 spA[CHUNK / 2];
    __shared__ __align__(16) ulonglong2 spB[CHUNK / 2];
    const int b  = blockIdx.z;
    const int c  = blockIdx.y;
    const int n0 = c * CHUNK;

    const float* pcb = pc + ((size_t)b * NN + n0) * 3;
    for (int i = threadIdx.x; i < CHUNK / 2; i += blockDim.x) {
        float x0 = pcb[6 * i + 0], y0 = pcb[6 * i + 1], z0 = pcb[6 * i + 2];
        float x1 = pcb[6 * i + 3], y1 = pcb[6 * i + 4], z1 = pcb[6 * i + 5];
        float pn0 = __fadd_rn(__fadd_rn(__fmul_rn(x0, x0), __fmul_rn(y0, y0)),
                              __fmul_rn(z0, z0));
        float pn1 = __fadd_rn(__fadd_rn(__fmul_rn(x1, x1), __fmul_rn(y1, y1)),
                              __fmul_rn(z1, z1));
        ((float4*)spA)[i] = make_float4(-2.0f * x0, -2.0f * x1, -2.0f * y0, -2.0f * y1);
        ((float4*)spB)[i] = make_float4(-2.0f * z0, -2.0f * z1, pn0, pn1);
    }
    __syncthreads();

    const int k = blockIdx.x * blockDim.x + threadIdx.x;
    const float bx = basis[k * 3 + 0];
    const float by = basis[k * 3 + 1];
    const float bz = basis[k * 3 + 2];
    const float bn = __fadd_rn(__fadd_rn(__fmul_rn(bx, bx), __fmul_rn(by, by)),
                               __fmul_rn(bz, bz));
    const ull bxp = pk2(bx, bx);
    const ull byp = pk2(by, by);
    const ull bzp = pk2(bz, bz);
    const ull bnp = pk2(bn, bn);

    float best = FLT_MAX;
    int   bg   = 0;                       // winning GROUP (8 points) index
    #pragma unroll 2
    for (int g = 0; g < CHUNK / 8; g++) {
        float m8;
        {
            ull d0, d1, d2, d3;
            {
                ulonglong2 qa = spA[4 * g + 0];
                ulonglong2 qb = spB[4 * g + 0];
                ull cr, t;
                MUL2(cr, bxp, qa.x); FMA2(cr, byp, qa.y, cr); FMA2(cr, bzp, qb.x, cr);
                ADD2(t, bnp, qb.y);  ADD2(d0, cr, t);
            }
            {
                ulonglong2 qa = spA[4 * g + 1];
                ulonglong2 qb = spB[4 * g + 1];
                ull cr, t;
                MUL2(cr, bxp, qa.x); FMA2(cr, byp, qa.y, cr); FMA2(cr, bzp, qb.x, cr);
                ADD2(t, bnp, qb.y);  ADD2(d1, cr, t);
            }
            {
                ulonglong2 qa = spA[4 * g + 2];
                ulonglong2 qb = spB[4 * g + 2];
                ull cr, t;
                MUL2(cr, bxp, qa.x); FMA2(cr, byp, qa.y, cr); FMA2(cr, bzp, qb.x, cr);
                ADD2(t, bnp, qb.y);  ADD2(d2, cr, t);
            }
            {
                ulonglong2 qa = spA[4 * g + 3];
                ulonglong2 qb = spB[4 * g + 3];
                ull cr, t;
                MUL2(cr, bxp, qa.x); FMA2(cr, byp, qa.y, cr); FMA2(cr, bzp, qb.x, cr);
                ADD2(t, bnp, qb.y);  ADD2(d3, cr, t);
            }
            float a0, a1, b0, b1, c0, c1, e0, e1;
            upk2(a0, a1, d0);
            upk2(b0, b1, d1);
            upk2(c0, c1, d2);
            upk2(e0, e1, d3);
            float mA = fminf(fminf(a0, a1), fminf(b0, b1));
            float mB = fminf(fminf(c0, c1), fminf(e0, e1));
            m8 = fminf(mA, mB);
        }
        bg   = (m8 < best) ? g : bg;      // strict < => earliest group on tie
        best = fminf(best, m8);
    }

    // resolve index inside the winning group: first j with d == best
    int bi = 0;
    {
        bool found = false;
        #pragma unroll
        for (int p = 0; p < 4; p++) {
            ulonglong2 qa = spA[4 * bg + p];
            ulonglong2 qb = spB[4 * bg + p];
            float m2x0, m2x1, m2y0, m2y1, m2z0, m2z1, pn0, pn1;
            upk2(m2x0, m2x1, qa.x);
            upk2(m2y0, m2y1, qa.y);
            upk2(m2z0, m2z1, qb.x);
            upk2(pn0,  pn1,  qb.y);
            float c0 = __fmaf_rn(bz, m2z0, __fmaf_rn(by, m2y0, __fmul_rn(bx, m2x0)));
            float d0 = __fadd_rn(c0, __fadd_rn(bn, pn0));
            float c1 = __fmaf_rn(bz, m2z1, __fmaf_rn(by, m2y1, __fmul_rn(bx, m2x1)));
            float d1 = __fadd_rn(c1, __fadd_rn(bn, pn1));
            if (!found && d0 == best) { bi = 8 * bg + 2 * p;     found = true; }
            if (!found && d1 == best) { bi = 8 * bg + 2 * p + 1; found = true; }
        }
    }

    const int o = (b * KK + k) * NCHUNK + c;
    g_best[o] = best;
    g_bidx[o] = n0 + bi;
}

// ============================================================
// Kernel 2: combine chunk partials (ascending order, strict <),
// gather nearest point, write bps row: [dists(4096) | deltas(3*4096)]
// ============================================================
__global__ void k_finish(const float* __restrict__ pc,
                         const float* __restrict__ basis,
                         float* __restrict__ out_bps) {
    const int t = blockIdx.x * blockDim.x + threadIdx.x;
    if (t >= BB * KK) return;
    const int b = t >> 12;
    const int k = t & (KK - 1);

    float best = g_best[t * NCHUNK];
    int   bi   = g_bidx[t * NCHUNK];
    #pragma unroll
    for (int c = 1; c < NCHUNK; c++) {
        float v = g_best[t * NCHUNK + c];
        int   i = g_bidx[t * NCHUNK + c];
        if (v < best) { best = v; bi = i; }
    }

    const float* p = pc + ((size_t)b * NN + bi) * 3;
    const float dx = __fadd_rn(p[0], -basis[k * 3 + 0]);
    const float dy = __fadd_rn(p[1], -basis[k * 3 + 1]);
    const float dz = __fadd_rn(p[2], -basis[k * 3 + 2]);
    const float ss = __fadd_rn(__fadd_rn(__fmul_rn(dx, dx), __fmul_rn(dy, dy)),
                               __fmul_rn(dz, dz));
    const float dist = sqrtf(ss);

    float* row = out_bps + (size_t)b * IN1;
    row[k]              = dist;
    row[KK + 3 * k + 0] = dx;
    row[KK + 3 * k + 1] = dy;
    row[KK + 3 * k + 2] = dz;
}

// ============================================================
// Split-K GEMM, 2 cols/thread, f32x2 acc. grid (H/512, INsz/CI)
// ============================================================
template <int CI>
__global__ void k_gemm2c(const float* __restrict__ A,
                         const float* __restrict__ W,
                         float* __restrict__ part,
                         int INsz, int H) {
    __shared__ __align__(16) float sA[CI * 16];
    const int i0 = blockIdx.y * CI;

    for (int idx = threadIdx.x; idx < CI * 16; idx += 256) {
        const int m  = idx / CI;
        const int il = idx % CI;
        sA[il * 16 + m] = A[(size_t)m * INsz + i0 + il];
    }
    __syncthreads();

    const int j = blockIdx.x * 512 + threadIdx.x;
    ull acc[16];
    #pragma unroll
    for (int m = 0; m < 16; m++) acc[m] = 0ull;

    const float* wp = W + (size_t)i0 * H + j;
    #pragma unroll 4
    for (int il = 0; il < CI; il++) {
        const float wa = wp[0];
        const float wb = wp[256];
        wp += H;
        const ull wpa = pk2(wa, wa);
        const ull wpb = pk2(wb, wb);
        const ulonglong2* ap = (const ulonglong2*)(sA + il * 16);
        ulonglong2 a0 = ap[0], a1 = ap[1], a2 = ap[2], a3 = ap[3];
        FMA2(acc[0],  a0.x, wpa, acc[0]);
        FMA2(acc[1],  a0.y, wpa, acc[1]);
        FMA2(acc[2],  a1.x, wpa, acc[2]);
        FMA2(acc[3],  a1.y, wpa, acc[3]);
        FMA2(acc[4],  a2.x, wpa, acc[4]);
        FMA2(acc[5],  a2.y, wpa, acc[5]);
        FMA2(acc[6],  a3.x, wpa, acc[6]);
        FMA2(acc[7],  a3.y, wpa, acc[7]);
        FMA2(acc[8],  a0.x, wpb, acc[8]);
        FMA2(acc[9],  a0.y, wpb, acc[9]);
        FMA2(acc[10], a1.x, wpb, acc[10]);
        FMA2(acc[11], a1.y, wpb, acc[11]);
        FMA2(acc[12], a2.x, wpb, acc[12]);
        FMA2(acc[13], a2.y, wpb, acc[13]);
        FMA2(acc[14], a3.x, wpb, acc[14]);
        FMA2(acc[15], a3.y, wpb, acc[15]);
    }

    float* pp = part + ((size_t)blockIdx.y * 16) * H + j;
    #pragma unroll
    for (int t = 0; t < 8; t++) {
        float lo, hi;
        upk2(lo, hi, acc[t]);
        pp[(size_t)(2 * t)     * H] = lo;
        pp[(size_t)(2 * t + 1) * H] = hi;
        upk2(lo, hi, acc[8 + t]);
        pp[(size_t)(2 * t)     * H + 256] = lo;
        pp[(size_t)(2 * t + 1) * H + 256] = hi;
    }
}

// ============================================================
// Split-K GEMM, 1 col/thread (H=256 tail). grid (H/256, INsz/CI)
// ============================================================
template <int CI>
__global__ void k_gemm1c(const float* __restrict__ A,
                         const float* __restrict__ W,
                         float* __restrict__ part,
                         int INsz, int H) {
    __shared__ __align__(16) float sA[CI * 16];
    const int i0 = blockIdx.y * CI;

    for (int idx = threadIdx.x; idx < CI * 16; idx += 256) {
        const int m  = idx / CI;
        const int il = idx % CI;
        sA[il * 16 + m] = A[(size_t)m * INsz + i0 + il];
    }
    __syncthreads();

    const int j = blockIdx.x * 256 + threadIdx.x;
    ull acc[8];
    #pragma unroll
    for (int m = 0; m < 8; m++) acc[m] = 0ull;

    const float* wp = W + (size_t)i0 * H + j;
    #pragma unroll 4
    for (int il = 0; il < CI; il++) {
        const float w = *wp;
        wp += H;
        const ull wpk = pk2(w, w);
        const ulonglong2* ap = (const ulonglong2*)(sA + il * 16);
        ulonglong2 a0 = ap[0], a1 = ap[1], a2 = ap[2], a3 = ap[3];
        FMA2(acc[0], a0.x, wpk, acc[0]);
        FMA2(acc[1], a0.y, wpk, acc[1]);
        FMA2(acc[2], a1.x, wpk, acc[2]);
        FMA2(acc[3], a1.y, wpk, acc[3]);
        FMA2(acc[4], a2.x, wpk, acc[4]);
        FMA2(acc[5], a2.y, wpk, acc[5]);
        FMA2(acc[6], a3.x, wpk, acc[6]);
        FMA2(acc[7], a3.y, wpk, acc[7]);
    }

    float* pp = part + ((size_t)blockIdx.y * 16) * H + j;
    #pragma unroll
    for (int t = 0; t < 8; t++) {
        float lo, hi;
        upk2(lo, hi, acc[t]);
        pp[(size_t)(2 * t)     * H] = lo;
        pp[(size_t)(2 * t + 1) * H] = hi;
    }
}

// ============================================================
// Two-stage deterministic reduces.
// Stage 1: each thread sums P consecutive parts of one element.
//   t in [0, ngroups*total): group = t / total, el = t % total
// ============================================================
__global__ void k_red_s1(const float* __restrict__ part,
                         float* __restrict__ tmp,
                         int total, int P) {
    const int t = blockIdx.x * 256 + threadIdx.x;
    const int group = t / total;
    const int el    = t - group * total;
    const float* p = part + (size_t)group * P * total + el;
    float s = 0.0f;
    #pragma unroll 8
    for (int q = 0; q < P; q++) s += p[(size_t)q * total];
    tmp[t] = s;
}

// Stage 2: sum ngroups partials + bias (+ lrelu)
__global__ void k_red_s2(const float* __restrict__ tmp,
                         const float* __restrict__ bias,
                         float* __restrict__ outv,
                         int total, int H, int ngroups, int do_lrelu) {
    const int t = blockIdx.x * 256 + threadIdx.x;
    if (t >= total) return;
    float s = 0.0f;
    #pragma unroll 8
    for (int g = 0; g < ngroups; g++) s += tmp[(size_t)g * total + t];
    s += bias[t & (H - 1)];
    if (do_lrelu && s < 0.0f) s *= 0.2f;
    outv[t] = s;
}

// Single-stage reduce for the small final layer
__global__ void k_reduce(const float* __restrict__ part,
                         const float* __restrict__ bias,
                         float* __restrict__ outv,
                         int H, int nparts, int do_lrelu) {
    const int t = blockIdx.x * blockDim.x + threadIdx.x;
    const int total = BB * H;
    if (t >= total) return;
    float s = 0.0f;
    #pragma unroll 8
    for (int p = 0; p < nparts; p++) s += part[(size_t)p * total + t];
    s += bias[t & (H - 1)];
    if (do_lrelu && s < 0.0f) s *= 0.2f;
    outv[t] = s;
}

// ============================================================
extern "C" void kernel_launch(void* const* d_in, const int* in_sizes, int n_in,
                              void* d_out, int out_size) {
    const float* pc    = (const float*)d_in[0];
    const float* basis = (const float*)d_in[1];
    const float* W1    = (const float*)d_in[2];
    const float* b1    = (const float*)d_in[3];
    const float* W2    = (const float*)d_in[4];
    const float* b2    = (const float*)d_in[5];
    const float* W3    = (const float*)d_in[6];
    const float* b3    = (const float*)d_in[7];

    float* out = (float*)d_out;            // global_feature: [16][256]
    float* bps = out + BB * OUTD;          // bps_feature:    [16][16384]

    float *p1, *p2, *p3, *h1, *h2, *tmp;
    cudaGetSymbolAddress((void**)&p1, g_part1);
    cudaGetSymbolAddress((void**)&p2, g_part2);
    cudaGetSymbolAddress((void**)&p3, g_part3);
    cudaGetSymbolAddress((void**)&h1, g_h1);
    cudaGetSymbolAddress((void**)&h2, g_h2);
    cudaGetSymbolAddress((void**)&tmp, g_tmp);

    k_argmin<<<dim3(KK / 256, NCHUNK, BB), 256>>>(pc, basis);
    k_finish<<<(BB * KK) / 256, 256>>>(pc, basis, bps);

    // layer 1: [16,16384] @ [16384,1024] — 256 blocks, 128-way split-K
    k_gemm2c<128><<<dim3(H1 / 512, IN1 / 128), 256>>>(bps, W1, p1, IN1, H1);
    k_red_s1<<<(16 * BB * H1) / 256, 256>>>(p1, tmp, BB * H1, 8);     // 128 -> 16
    k_red_s2<<<(BB * H1) / 256, 256>>>(tmp, b1, h1, BB * H1, H1, 16, 1);

    // layer 2: [16,1024] @ [1024,512] — 64 blocks, 64-way split-K
    k_gemm2c<16><<<dim3(H2 / 512, H1 / 16), 256>>>(h1, W2, p2, H1, H2);
    k_red_s1<<<(8 * BB * H2) / 256, 256>>>(p2, tmp, BB * H2, 8);      // 64 -> 8
    k_red_s2<<<(BB * H2) / 256, 256>>>(tmp, b2, h2, BB * H2, H2, 8, 1);

    // layer 3: [16,512] @ [512,256] — 16 blocks, 16-way split-K
    k_gemm1c<32><<<dim3(OUTD / 256, H2 / 32), 256>>>(h2, W3, p3, H2, OUTD);
    k_reduce<<<(BB * OUTD) / 256, 256>>>(p3, b3, out, OUTD, 16, 0);
}

// round 7
// speedup vs baseline: 1.0331x; 1.0331x over previous
#include <cuda_runtime.h>
#include <math.h>
#include <float.h>

#define BB   16
#define NN   4096
#define KK   4096
#define NCHUNK 4
#define CHUNK  1024      // NN / NCHUNK
#define QQ   2           // queries (basis points) per thread
#define IN1  16384
#define H1   1024
#define H2   512
#define OUTD 256

typedef unsigned long long ull;

#define FMA2(out, a, b, c) asm("fma.rn.f32x2 %0, %1, %2, %3;" : "=l"(out) : "l"(a), "l"(b), "l"(c))
#define MUL2(out, a, b)    asm("mul.rn.f32x2 %0, %1, %2;"     : "=l"(out) : "l"(a), "l"(b))
#define ADD2(out, a, b)    asm("add.rn.f32x2 %0, %1, %2;"     : "=l"(out) : "l"(a), "l"(b))

__device__ __forceinline__ ull pk2(float lo, float hi) {
    ull r; asm("mov.b64 %0, {%1, %2};" : "=l"(r) : "f"(lo), "f"(hi)); return r;
}
__device__ __forceinline__ void upk2(float& lo, float& hi, ull v) {
    asm("mov.b64 {%0, %1}, %2;" : "=f"(lo), "=f"(hi) : "l"(v));
}

// ---- scratch ----
__device__ __align__(16) float2 g_bi  [BB * KK * NCHUNK];   // (best, idx-bits)
__device__ __align__(16) float  g_part1[128 * BB * H1];     // 8 MB
__device__ __align__(16) float  g_tmp  [16 * BB * H1];      // 1 MB
__device__ __align__(16) float  g_h1[BB * H1];
__device__ __align__(16) float  g_part2[64 * BB * H2];
__device__ __align__(16) float  g_h2[BB * H2];
__device__ __align__(16) float  g_part3[16 * BB * OUTD];

// shared tiles for argmin (file-scope type for helper fn)
struct ArgminSmem {
    ulonglong2 spA[CHUNK / 2];
    ulonglong2 spB[CHUNK / 2];
};

// recompute scalar distances inside winning group, return first index == best
__device__ __forceinline__ int resolve_group(const ArgminSmem* s, int bg, float best,
                                             float bx, float by, float bz, float bn) {
    int bi = 0;
    bool found = false;
    #pragma unroll
    for (int p = 0; p < 4; p++) {
        ulonglong2 qa = s->spA[4 * bg + p];
        ulonglong2 qb = s->spB[4 * bg + p];
        float m2x0, m2x1, m2y0, m2y1, m2z0, m2z1, pn0, pn1;
        upk2(m2x0, m2x1, qa.x);
        upk2(m2y0, m2y1, qa.y);
        upk2(m2z0, m2z1, qb.x);
        upk2(pn0,  pn1,  qb.y);
        float c0 = __fmaf_rn(bz, m2z0, __fmaf_rn(by, m2y0, __fmul_rn(bx, m2x0)));
        float d0 = __fadd_rn(c0, __fadd_rn(bn, pn0));
        float c1 = __fmaf_rn(bz, m2z1, __fmaf_rn(by, m2y1, __fmul_rn(bx, m2x1)));
        float d1 = __fadd_rn(c1, __fadd_rn(bn, pn1));
        if (!found && d0 == best) { bi = 8 * bg + 2 * p;     found = true; }
        if (!found && d1 == best) { bi = 8 * bg + 2 * p + 1; found = true; }
    }
    return bi;
}

// ============================================================
// Kernel 1: partial argmin over an N-chunk, bit-exact reference
// arithmetic, 2 pts per f32x2 op, 2 QUERIES per thread (amortizes
// each smem load over both), group-of-8 deferred min per query.
//   d = rn(fma(bz,-2z,fma(by,-2y,rn(bx*-2x))) + rn(bn+pn))
//     == reference fma(-2,cr,bn+pn) bit-exactly.
// grid: (KK/(256*QQ), NCHUNK, BB) = (8,4,16), block 256
// ============================================================
__global__ void k_argmin(const float* __restrict__ pc,
                         const float* __restrict__ basis) {
    __shared__ ArgminSmem s;
    const int b  = blockIdx.z;
    const int c  = blockIdx.y;
    const int n0 = c * CHUNK;

    const float* pcb = pc + ((size_t)b * NN + n0) * 3;
    for (int i = threadIdx.x; i < CHUNK / 2; i += blockDim.x) {
        float x0 = pcb[6 * i + 0], y0 = pcb[6 * i + 1], z0 = pcb[6 * i + 2];
        float x1 = pcb[6 * i + 3], y1 = pcb[6 * i + 4], z1 = pcb[6 * i + 5];
        float pn0 = __fadd_rn(__fadd_rn(__fmul_rn(x0, x0), __fmul_rn(y0, y0)),
                              __fmul_rn(z0, z0));
        float pn1 = __fadd_rn(__fadd_rn(__fmul_rn(x1, x1), __fmul_rn(y1, y1)),
                              __fmul_rn(z1, z1));
        ((float4*)s.spA)[i] = make_float4(-2.0f * x0, -2.0f * x1, -2.0f * y0, -2.0f * y1);
        ((float4*)s.spB)[i] = make_float4(-2.0f * z0, -2.0f * z1, pn0, pn1);
    }
    __syncthreads();

    const int k1 = blockIdx.x * blockDim.x + threadIdx.x;   // 0..2047
    const int k2 = k1 + KK / QQ;                            // +2048

    const float bx1 = basis[k1 * 3 + 0], by1 = basis[k1 * 3 + 1], bz1 = basis[k1 * 3 + 2];
    const float bx2 = basis[k2 * 3 + 0], by2 = basis[k2 * 3 + 1], bz2 = basis[k2 * 3 + 2];
    const float bn1 = __fadd_rn(__fadd_rn(__fmul_rn(bx1, bx1), __fmul_rn(by1, by1)),
                                __fmul_rn(bz1, bz1));
    const float bn2 = __fadd_rn(__fadd_rn(__fmul_rn(bx2, bx2), __fmul_rn(by2, by2)),
                                __fmul_rn(bz2, bz2));
    const ull bxp1 = pk2(bx1, bx1), byp1 = pk2(by1, by1), bzp1 = pk2(bz1, bz1), bnp1 = pk2(bn1, bn1);
    const ull bxp2 = pk2(bx2, bx2), byp2 = pk2(by2, by2), bzp2 = pk2(bz2, bz2), bnp2 = pk2(bn2, bn2);

    float best1 = FLT_MAX, best2 = FLT_MAX;
    int   bg1 = 0, bg2 = 0;

    #pragma unroll 2
    for (int g = 0; g < CHUNK / 8; g++) {
        ull e1[4], e2[4];
        #pragma unroll
        for (int p = 0; p < 4; p++) {
            ulonglong2 qa = s.spA[4 * g + p];
            ulonglong2 qb = s.spB[4 * g + p];
            ull cr, t;
            MUL2(cr, bxp1, qa.x); FMA2(cr, byp1, qa.y, cr); FMA2(cr, bzp1, qb.x, cr);
            ADD2(t, bnp1, qb.y);  ADD2(e1[p], cr, t);
            MUL2(cr, bxp2, qa.x); FMA2(cr, byp2, qa.y, cr); FMA2(cr, bzp2, qb.x, cr);
            ADD2(t, bnp2, qb.y);  ADD2(e2[p], cr, t);
        }
        {
            float a0, a1, b0, b1, c0, c1, d0, d1;
            upk2(a0, a1, e1[0]); upk2(b0, b1, e1[1]);
            upk2(c0, c1, e1[2]); upk2(d0, d1, e1[3]);
            float m8 = fminf(fminf(fminf(a0, a1), fminf(b0, b1)),
                             fminf(fminf(c0, c1), fminf(d0, d1)));
            bg1   = (m8 < best1) ? g : bg1;
            best1 = fminf(best1, m8);
        }
        {
            float a0, a1, b0, b1, c0, c1, d0, d1;
            upk2(a0, a1, e2[0]); upk2(b0, b1, e2[1]);
            upk2(c0, c1, e2[2]); upk2(d0, d1, e2[3]);
            float m8 = fminf(fminf(fminf(a0, a1), fminf(b0, b1)),
                             fminf(fminf(c0, c1), fminf(d0, d1)));
            bg2   = (m8 < best2) ? g : bg2;
            best2 = fminf(best2, m8);
        }
    }

    const int bi1 = resolve_group(&s, bg1, best1, bx1, by1, bz1, bn1);
    const int bi2 = resolve_group(&s, bg2, best2, bx2, by2, bz2, bn2);

    g_bi[(b * KK + k1) * NCHUNK + c] = make_float2(best1, __int_as_float(n0 + bi1));
    g_bi[(b * KK + k2) * NCHUNK + c] = make_float2(best2, __int_as_float(n0 + bi2));
}

// ============================================================
// Kernel 2: combine chunk partials (ascending order, strict <),
// gather nearest point, write bps row: [dists(4096) | deltas(3*4096)]
// ============================================================
__global__ void k_finish(const float* __restrict__ pc,
                         const float* __restrict__ basis,
                         float* __restrict__ out_bps) {
    const int t = blockIdx.x * blockDim.x + threadIdx.x;
    if (t >= BB * KK) return;
    const int b = t >> 12;
    const int k = t & (KK - 1);

    const float4* q = (const float4*)(g_bi + (size_t)t * NCHUNK);
    float4 v01 = q[0];     // (best0, idx0, best1, idx1)
    float4 v23 = q[1];     // (best2, idx2, best3, idx3)

    float best = v01.x;
    int   bi   = __float_as_int(v01.y);
    if (v01.z < best) { best = v01.z; bi = __float_as_int(v01.w); }
    if (v23.x < best) { best = v23.x; bi = __float_as_int(v23.y); }
    if (v23.z < best) { best = v23.z; bi = __float_as_int(v23.w); }

    const float* p = pc + ((size_t)b * NN + bi) * 3;
    const float dx = __fadd_rn(p[0], -basis[k * 3 + 0]);
    const float dy = __fadd_rn(p[1], -basis[k * 3 + 1]);
    const float dz = __fadd_rn(p[2], -basis[k * 3 + 2]);
    const float ss = __fadd_rn(__fadd_rn(__fmul_rn(dx, dx), __fmul_rn(dy, dy)),
                               __fmul_rn(dz, dz));
    const float dist = sqrtf(ss);

    float* row = out_bps + (size_t)b * IN1;
    row[k]              = dist;
    row[KK + 3 * k + 0] = dx;
    row[KK + 3 * k + 1] = dy;
    row[KK + 3 * k + 2] = dz;
}

// ============================================================
// Split-K GEMM, 2 cols/thread, f32x2 acc. grid (H/512, INsz/CI)
// ============================================================
template <int CI>
__global__ void k_gemm2c(const float* __restrict__ A,
                         const float* __restrict__ W,
                         float* __restrict__ part,
                         int INsz, int H) {
    __shared__ __align__(16) float sA[CI * 16];
    const int i0 = blockIdx.y * CI;

    for (int idx = threadIdx.x; idx < CI * 16; idx += 256) {
        const int m  = idx / CI;
        const int il = idx % CI;
        sA[il * 16 + m] = A[(size_t)m * INsz + i0 + il];
    }
    __syncthreads();

    const int j = blockIdx.x * 512 + threadIdx.x;
    ull acc[16];
    #pragma unroll
    for (int m = 0; m < 16; m++) acc[m] = 0ull;

    const float* wp = W + (size_t)i0 * H + j;
    #pragma unroll 4
    for (int il = 0; il < CI; il++) {
        const float wa = wp[0];
        const float wb = wp[256];
        wp += H;
        const ull wpa = pk2(wa, wa);
        const ull wpb = pk2(wb, wb);
        const ulonglong2* ap = (const ulonglong2*)(sA + il * 16);
        ulonglong2 a0 = ap[0], a1 = ap[1], a2 = ap[2], a3 = ap[3];
        FMA2(acc[0],  a0.x, wpa, acc[0]);
        FMA2(acc[1],  a0.y, wpa, acc[1]);
        FMA2(acc[2],  a1.x, wpa, acc[2]);
        FMA2(acc[3],  a1.y, wpa, acc[3]);
        FMA2(acc[4],  a2.x, wpa, acc[4]);
        FMA2(acc[5],  a2.y, wpa, acc[5]);
        FMA2(acc[6],  a3.x, wpa, acc[6]);
        FMA2(acc[7],  a3.y, wpa, acc[7]);
        FMA2(acc[8],  a0.x, wpb, acc[8]);
        FMA2(acc[9],  a0.y, wpb, acc[9]);
        FMA2(acc[10], a1.x, wpb, acc[10]);
        FMA2(acc[11], a1.y, wpb, acc[11]);
        FMA2(acc[12], a2.x, wpb, acc[12]);
        FMA2(acc[13], a2.y, wpb, acc[13]);
        FMA2(acc[14], a3.x, wpb, acc[14]);
        FMA2(acc[15], a3.y, wpb, acc[15]);
    }

    float* pp = part + ((size_t)blockIdx.y * 16) * H + j;
    #pragma unroll
    for (int t = 0; t < 8; t++) {
        float lo, hi;
        upk2(lo, hi, acc[t]);
        pp[(size_t)(2 * t)     * H] = lo;
        pp[(size_t)(2 * t + 1) * H] = hi;
        upk2(lo, hi, acc[8 + t]);
        pp[(size_t)(2 * t)     * H + 256] = lo;
        pp[(size_t)(2 * t + 1) * H + 256] = hi;
    }
}

// ============================================================
// Split-K GEMM, 1 col/thread (H=256 tail). grid (H/256, INsz/CI)
// ============================================================
template <int CI>
__global__ void k_gemm1c(const float* __restrict__ A,
                         const float* __restrict__ W,
                         float* __restrict__ part,
                         int INsz, int H) {
    __shared__ __align__(16) float sA[CI * 16];
    const int i0 = blockIdx.y * CI;

    for (int idx = threadIdx.x; idx < CI * 16; idx += 256) {
        const int m  = idx / CI;
        const int il = idx % CI;
        sA[il * 16 + m] = A[(size_t)m * INsz + i0 + il];
    }
    __syncthreads();

    const int j = blockIdx.x * 256 + threadIdx.x;
    ull acc[8];
    #pragma unroll
    for (int m = 0; m < 8; m++) acc[m] = 0ull;

    const float* wp = W + (size_t)i0 * H + j;
    #pragma unroll 4
    for (int il = 0; il < CI; il++) {
        const float w = *wp;
        wp += H;
        const ull wpk = pk2(w, w);
        const ulonglong2* ap = (const ulonglong2*)(sA + il * 16);
        ulonglong2 a0 = ap[0], a1 = ap[1], a2 = ap[2], a3 = ap[3];
        FMA2(acc[0], a0.x, wpk, acc[0]);
        FMA2(acc[1], a0.y, wpk, acc[1]);
        FMA2(acc[2], a1.x, wpk, acc[2]);
        FMA2(acc[3], a1.y, wpk, acc[3]);
        FMA2(acc[4], a2.x, wpk, acc[4]);
        FMA2(acc[5], a2.y, wpk, acc[5]);
        FMA2(acc[6], a3.x, wpk, acc[6]);
        FMA2(acc[7], a3.y, wpk, acc[7]);
    }

    float* pp = part + ((size_t)blockIdx.y * 16) * H + j;
    #pragma unroll
    for (int t = 0; t < 8; t++) {
        float lo, hi;
        upk2(lo, hi, acc[t]);
        pp[(size_t)(2 * t)     * H] = lo;
        pp[(size_t)(2 * t + 1) * H] = hi;
    }
}

// ============================================================
// Two-stage deterministic reduces, float4-vectorized.
// Stage 1: thread sums P consecutive parts of one float4 element.
// ============================================================
__global__ void k_red_s1(const float4* __restrict__ part,
                         float4* __restrict__ tmp,
                         int total4, int P) {
    const int t = blockIdx.x * 256 + threadIdx.x;
    const int group = t / total4;
    const int el    = t - group * total4;
    const float4* p = part + (size_t)group * P * total4 + el;
    float4 s = make_float4(0.f, 0.f, 0.f, 0.f);
    #pragma unroll 8
    for (int q = 0; q < P; q++) {
        float4 v = p[(size_t)q * total4];
        s.x += v.x; s.y += v.y; s.z += v.z; s.w += v.w;
    }
    tmp[t] = s;
}

// Stage 2: sum ngroups float4 partials + bias (+ lrelu)
__global__ void k_red_s2(const float4* __restrict__ tmp,
                         const float4* __restrict__ bias,
                         float4* __restrict__ outv,
                         int total4, int H4, int ngroups, int do_lrelu) {
    const int t = blockIdx.x * 256 + threadIdx.x;
    if (t >= total4) return;
    float4 s = make_float4(0.f, 0.f, 0.f, 0.f);
    #pragma unroll 8
    for (int g = 0; g < ngroups; g++) {
        float4 v = tmp[(size_t)g * total4 + t];
        s.x += v.x; s.y += v.y; s.z += v.z; s.w += v.w;
    }
    float4 bv = bias[t & (H4 - 1)];
    s.x += bv.x; s.y += bv.y; s.z += bv.z; s.w += bv.w;
    if (do_lrelu) {
        if (s.x < 0.f) s.x *= 0.2f;
        if (s.y < 0.f) s.y *= 0.2f;
        if (s.z < 0.f) s.z *= 0.2f;
        if (s.w < 0.f) s.w *= 0.2f;
    }
    outv[t] = s;
}

// Single-stage float4 reduce for the final layer (no lrelu)
__global__ void k_reduce4(const float4* __restrict__ part,
                          const float4* __restrict__ bias,
                          float4* __restrict__ outv,
                          int total4, int H4, int nparts) {
    const int t = blockIdx.x * 256 + threadIdx.x;
    if (t >= total4) return;
    float4 s = make_float4(0.f, 0.f, 0.f, 0.f);
    #pragma unroll 8
    for (int p = 0; p < nparts; p++) {
        float4 v = part[(size_t)p * total4 + t];
        s.x += v.x; s.y += v.y; s.z += v.z; s.w += v.w;
    }
    float4 bv = bias[t & (H4 - 1)];
    s.x += bv.x; s.y += bv.y; s.z += bv.z; s.w += bv.w;
    outv[t] = s;
}

// ============================================================
extern "C" void kernel_launch(void* const* d_in, const int* in_sizes, int n_in,
                              void* d_out, int out_size) {
    const float* pc    = (const float*)d_in[0];
    const float* basis = (const float*)d_in[1];
    const float* W1    = (const float*)d_in[2];
    const float* b1    = (const float*)d_in[3];
    const float* W2    = (const float*)d_in[4];
    const float* b2    = (const float*)d_in[5];
    const float* W3    = (const float*)d_in[6];
    const float* b3    = (const float*)d_in[7];

    float* out = (float*)d_out;            // global_feature: [16][256]
    float* bps = out + BB * OUTD;          // bps_feature:    [16][16384]

    float *p1, *p2, *p3, *h1, *h2, *tmp;
    cudaGetSymbolAddress((void**)&p1, g_part1);
    cudaGetSymbolAddress((void**)&p2, g_part2);
    cudaGetSymbolAddress((void**)&p3, g_part3);
    cudaGetSymbolAddress((void**)&h1, g_h1);
    cudaGetSymbolAddress((void**)&h2, g_h2);
    cudaGetSymbolAddress((void**)&tmp, g_tmp);

    k_argmin<<<dim3(KK / (256 * QQ), NCHUNK, BB), 256>>>(pc, basis);
    k_finish<<<(BB * KK) / 256, 256>>>(pc, basis, bps);

    // layer 1: [16,16384] @ [16384,1024] — 256 blocks, 128-way split-K
    k_gemm2c<128><<<dim3(H1 / 512, IN1 / 128), 256>>>(bps, W1, p1, IN1, H1);
    k_red_s1<<<(16 * BB * H1 / 4) / 256, 256>>>((const float4*)p1, (float4*)tmp, BB * H1 / 4, 8);
    k_red_s2<<<(BB * H1 / 4) / 256, 256>>>((const float4*)tmp, (const float4*)b1, (float4*)h1,
                                           BB * H1 / 4, H1 / 4, 16, 1);

    // layer 2: [16,1024] @ [1024,512] — 64 blocks, 64-way split-K
    k_gemm2c<16><<<dim3(H2 / 512, H1 / 16), 256>>>(h1, W2, p2, H1, H2);
    k_red_s1<<<(8 * BB * H2 / 4) / 256, 256>>>((const float4*)p2, (float4*)tmp, BB * H2 / 4, 8);
    k_red_s2<<<(BB * H2 / 4 + 255) / 256, 256>>>((const float4*)tmp, (const float4*)b2, (float4*)h2,
                                                 BB * H2 / 4, H2 / 4, 8, 1);

    // layer 3: [16,512] @ [512,256] — 16 blocks, 16-way split-K
    k_gemm1c<32><<<dim3(OUTD / 256, H2 / 32), 256>>>(h2, W3, p3, H2, OUTD);
    k_reduce4<<<(BB * OUTD / 4 + 255) / 256, 256>>>((const float4*)p3, (const float4*)b3, (float4*)out,
                                                    BB * OUTD / 4, OUTD / 4, 16);
}